// round 6
// baseline (speedup 1.0000x reference)
#include <cuda_runtime.h>
#include <cuda_bf16.h>

#define BB 32
#define CC 32
#define HH 480
#define WW 480
#define LL 120
#define HALF 60
#define PLANE (HH*WW)
#define RB 60            // reduce blocks per batch (8 rows each)

// per-(batch, reduce-block) partials: [cnt, sum_y, sum_x].
// Fully rewritten every replay before being read -> no zero-init, no atomics.
__device__ float g_part[BB * RB * 3];

// ---------------------------------------------------------------------------
// Kernel 1: masked centroid partials over channel-1 plane.
// Grid (RB, BB), block 256 (8 warps). Warp w owns row blockIdx.x*8 + w.
// Channel 1 is exactly {0.0, 1.0}, so mask == value: branch-free FMA stream.
// ---------------------------------------------------------------------------
__global__ void __launch_bounds__(256) reduce_pos_kernel(const float* __restrict__ in) {
    const int b    = blockIdx.y;
    const int w    = threadIdx.x >> 5;
    const int lane = threadIdx.x & 31;
    const int y    = blockIdx.x * 8 + w;

    const float4* __restrict__ row =
        (const float4*)(in + (size_t)b * CC * PLANE + (size_t)PLANE + (size_t)y * WW);

    float c = 0.0f, sx = 0.0f;
    #pragma unroll
    for (int k = 0; k < 4; k++) {
        const int xi = lane + 32 * k;          // float4 index in row, 120 per row
        if (xi < WW / 4) {
            float4 v  = row[xi];
            float  s4 = (v.x + v.y) + (v.z + v.w);
            c  += s4;
            sx += (float)(4 * xi) * s4 + (v.y + 2.0f * v.z + 3.0f * v.w);
        }
    }
    float sy = (float)y * c;                   // row constant per warp

    #pragma unroll
    for (int o = 16; o > 0; o >>= 1) {
        c  += __shfl_down_sync(0xffffffffu, c,  o);
        sy += __shfl_down_sync(0xffffffffu, sy, o);
        sx += __shfl_down_sync(0xffffffffu, sx, o);
    }
    __shared__ float s[3][8];
    if (lane == 0) { s[0][w] = c; s[1][w] = sy; s[2][w] = sx; }
    __syncthreads();
    if (threadIdx.x == 0) {
        float cc = 0.0f, ay = 0.0f, ax = 0.0f;
        #pragma unroll
        for (int i = 0; i < 8; i++) { cc += s[0][i]; ay += s[1][i]; ax += s[2][i]; }
        float* p = &g_part[(b * RB + blockIdx.x) * 3];
        p[0] = cc; p[1] = ay; p[2] = ax;
    }
}

// ---------------------------------------------------------------------------
// Kernel 2: crop + bilinear resize. Grid (CC, BB) = 1024 blocks, 256 threads.
// Block = one (b, c) plane: 57.6 KB of payload per prologue, vs 7.7 KB before.
//
// Fast path (ry==rx==120, unclamped window -> resize is the exact identity):
// warp-per-row strided copy, float4 stores, float4 loads when crop is 16B
// aligned. ~29/32 batches.
//
// Slow path: per-thread pixel loop with the 4-tap bilinear gather.
// Warp 0 redundantly finalizes the window from the 60 partials (L2-hot).
// ---------------------------------------------------------------------------
__global__ void __launch_bounds__(256) crop_resize_kernel(
        const float* __restrict__ in, float* __restrict__ out) {
    const int c = blockIdx.x;
    const int b = blockIdx.y;

    __shared__ int   swin[4];    // ys, ry, xs, rx
    __shared__ float sfac[2];    // fy, fx

    const int tid  = threadIdx.x;
    const int lane = tid & 31;
    const int w    = tid >> 5;

    if (tid < 32) {
        float cnt = 0.0f, sy = 0.0f, sx = 0.0f;
        if (lane < RB / 2) {
            const float* p = &g_part[(b * RB + lane) * 3];
            const float* q = &g_part[(b * RB + lane + RB / 2) * 3];
            cnt = p[0] + q[0];
            sy  = p[1] + q[1];
            sx  = p[2] + q[2];
        }
        #pragma unroll
        for (int o = 16; o > 0; o >>= 1) {
            cnt += __shfl_down_sync(0xffffffffu, cnt, o);
            sy  += __shfl_down_sync(0xffffffffu, sy,  o);
            sx  += __shfl_down_sync(0xffffffffu, sx,  o);
        }
        if (lane == 0) {
            float denom = fmaxf(cnt, 1.0f);
            // rintf = round-half-even, matching jnp.round
            int py = (cnt > 0.0f) ? (int)rintf(sy / denom) : (HH / 2);
            int px = (cnt > 0.0f) ? (int)rintf(sx / denom) : (WW / 2);
            int ys = max(py - HALF, 0);
            int ry = min(py + HALF, HH) - ys;
            int xs = max(px - HALF, 0);
            int rx = min(px + HALF, WW) - xs;
            swin[0] = ys; swin[1] = ry; swin[2] = xs; swin[3] = rx;
            sfac[0] = (float)ry / (float)LL;
            sfac[1] = (float)rx / (float)LL;
        }
    }
    __syncthreads();

    const int ys = swin[0], ry = swin[1], xs = swin[2], rx = swin[3];

    const float* __restrict__ img = in + ((size_t)b * CC + c) * PLANE;
    float* __restrict__ dst = out + ((size_t)b * CC + c) * (LL * LL);

    if (ry == LL && rx == LL) {
        // ---------------- fast path: exact crop copy ----------------
        const float* __restrict__ src = img + (size_t)ys * WW + xs;
        if (lane < LL / 4) {               // 30 active lanes
            const int ox = lane * 4;
            if ((xs & 3) == 0) {
                #pragma unroll 5
                for (int r = w; r < LL; r += 8) {
                    float4 v = *(const float4*)(src + (size_t)r * WW + ox);
                    *(float4*)(dst + r * LL + ox) = v;
                }
            } else {
                #pragma unroll 5
                for (int r = w; r < LL; r += 8) {
                    const float* p = src + (size_t)r * WW + ox;
                    float4 v;
                    v.x = p[0]; v.y = p[1]; v.z = p[2]; v.w = p[3];
                    *(float4*)(dst + r * LL + ox) = v;
                }
            }
        }
        return;
    }

    // ---------------- slow path: bilinear gather ----------------
    const float fy = sfac[0], fx = sfac[1];

    for (int i = tid; i < LL * LL; i += 256) {
        const int oy = i / LL;
        const int ox = i - oy * LL;

        float syv = fmaxf(((float)oy + 0.5f) * fy - 0.5f, 0.0f);
        float sxv = fmaxf(((float)ox + 0.5f) * fx - 0.5f, 0.0f);
        int y0 = (int)syv;               // >= 0 -> trunc == floor
        int x0 = (int)sxv;
        int y1 = min(y0 + 1, ry - 1);
        int x1 = min(x0 + 1, rx - 1);
        float wy = syv - (float)y0;
        float wx = sxv - (float)x0;

        const float* r0 = img + (size_t)(ys + y0) * WW + xs;
        const float* r1 = img + (size_t)(ys + y1) * WW + xs;
        float v00 = r0[x0], v01 = r0[x1];
        float v10 = r1[x0], v11 = r1[x1];

        float top = v00 * (1.0f - wx) + v01 * wx;
        float bot = v10 * (1.0f - wx) + v11 * wx;
        dst[i] = top * (1.0f - wy) + bot * wy;
    }
}

extern "C" void kernel_launch(void* const* d_in, const int* in_sizes, int n_in,
                              void* d_out, int out_size) {
    const float* in = (const float*)d_in[0];
    float* out = (float*)d_out;

    reduce_pos_kernel<<<dim3(RB, BB), 256>>>(in);
    crop_resize_kernel<<<dim3(CC, BB), 256>>>(in, out);
}

// round 7
// speedup vs baseline: 1.3128x; 1.3128x over previous
#include <cuda_runtime.h>
#include <cuda_bf16.h>

#define BB 32
#define CC 32
#define HH 480
#define WW 480
#define LL 120
#define HALF 60
#define PLANE (HH*WW)
#define RB 60            // reduce blocks per batch (8 rows each)

// per-(batch, reduce-block) partials: [cnt, sum_y, sum_x].
// Fully rewritten every replay before being read -> no zero-init needed.
__device__ float g_part[BB * RB * 3];
// per-batch crop window {ys, ry, xs, rx}, written by the last reduce block.
__device__ int4 g_pos[BB];
// last-block ticket; zero-initialized, reset to 0 by the finalizer each replay.
__device__ unsigned int g_ticket;

// ---------------------------------------------------------------------------
// Kernel 1: masked centroid partials over channel-1 plane + last-block window
// finalize. Grid (RB, BB), block 256 (8 warps). Warp w owns row bIdx.x*8+w.
// Channel 1 is exactly {0.0, 1.0}, so mask == value: branch-free FMA stream.
// ---------------------------------------------------------------------------
__global__ void __launch_bounds__(256) reduce_pos_kernel(const float* __restrict__ in) {
    const int b    = blockIdx.y;
    const int w    = threadIdx.x >> 5;
    const int lane = threadIdx.x & 31;
    const int y    = blockIdx.x * 8 + w;

    const float4* __restrict__ row =
        (const float4*)(in + (size_t)b * CC * PLANE + (size_t)PLANE + (size_t)y * WW);

    float c = 0.0f, sx = 0.0f;
    #pragma unroll
    for (int k = 0; k < 4; k++) {
        const int xi = lane + 32 * k;          // float4 index in row, 120 per row
        if (xi < WW / 4) {
            float4 v  = row[xi];
            float  s4 = (v.x + v.y) + (v.z + v.w);
            c  += s4;
            sx += (float)(4 * xi) * s4 + (v.y + 2.0f * v.z + 3.0f * v.w);
        }
    }
    float sy = (float)y * c;                   // row constant per warp

    #pragma unroll
    for (int o = 16; o > 0; o >>= 1) {
        c  += __shfl_down_sync(0xffffffffu, c,  o);
        sy += __shfl_down_sync(0xffffffffu, sy, o);
        sx += __shfl_down_sync(0xffffffffu, sx, o);
    }
    __shared__ float s[3][8];
    __shared__ bool  s_last;
    if (lane == 0) { s[0][w] = c; s[1][w] = sy; s[2][w] = sx; }
    __syncthreads();
    if (threadIdx.x == 0) {
        float cc = 0.0f, ay = 0.0f, ax = 0.0f;
        #pragma unroll
        for (int i = 0; i < 8; i++) { cc += s[0][i]; ay += s[1][i]; ax += s[2][i]; }
        float* p = &g_part[(b * RB + blockIdx.x) * 3];
        p[0] = cc; p[1] = ay; p[2] = ax;
        __threadfence();
        unsigned int t = atomicAdd(&g_ticket, 1u);
        s_last = (t == (unsigned int)(RB * BB - 1));
    }
    __syncthreads();

    if (!s_last) return;

    // ---- last block: finalize all 32 windows (warp handles 4 batches) ----
    for (int bb = w; bb < BB; bb += 8) {
        float cnt = 0.0f, ty = 0.0f, tx = 0.0f;
        if (lane < RB / 2) {
            const float* p = &g_part[(bb * RB + lane) * 3];
            const float* q = &g_part[(bb * RB + lane + RB / 2) * 3];
            cnt = p[0] + q[0];
            ty  = p[1] + q[1];
            tx  = p[2] + q[2];
        }
        #pragma unroll
        for (int o = 16; o > 0; o >>= 1) {
            cnt += __shfl_down_sync(0xffffffffu, cnt, o);
            ty  += __shfl_down_sync(0xffffffffu, ty,  o);
            tx  += __shfl_down_sync(0xffffffffu, tx,  o);
        }
        if (lane == 0) {
            float denom = fmaxf(cnt, 1.0f);
            // rintf = round-half-even, matching jnp.round
            int py = (cnt > 0.0f) ? (int)rintf(ty / denom) : (HH / 2);
            int px = (cnt > 0.0f) ? (int)rintf(tx / denom) : (WW / 2);
            int ys = max(py - HALF, 0);
            int ry = min(py + HALF, HH) - ys;
            int xs = max(px - HALF, 0);
            int rx = min(px + HALF, WW) - xs;
            g_pos[bb] = make_int4(ys, ry, xs, rx);
        }
    }
    if (threadIdx.x == 0) g_ticket = 0u;   // reset for next graph replay
}

// ---------------------------------------------------------------------------
// Kernel 2: crop + bilinear resize. Grid (LL/4, CC/4, BB), block (128,4)=512.
// Block = (b, 4 channels, 4 output rows). No smem, no syncthreads: the window
// is one uniform int4 LDG (warp-broadcast, L2-hot).
//
// Fast path (ry==rx==120: resize is the exact identity): warp = (ch, row)
// copy, float4 stores, float4 loads when the crop start is 16B aligned.
// Slow path: per-pixel 4-tap gather, weights reused across 4 channels.
// ---------------------------------------------------------------------------
__global__ void __launch_bounds__(512) crop_resize_kernel(
        const float* __restrict__ in, float* __restrict__ out) {
    const int b  = blockIdx.z;
    const int c0 = blockIdx.y * 4;

    const int4 win = g_pos[b];             // uniform load, broadcast
    const int ys = win.x, ry = win.y, xs = win.z, rx = win.w;

    if (ry == LL && rx == LL) {
        // ---------------- fast path: exact crop copy ----------------
        const int tid  = threadIdx.y * 128 + threadIdx.x;
        const int w    = tid >> 5;         // 0..15
        const int lane = tid & 31;
        if (lane >= LL / 4) return;        // 30 active lanes
        const int ch = w & 3;
        const int oy = blockIdx.x * 4 + (w >> 2);
        const int ox = lane * 4;

        const float* __restrict__ src =
            in + ((size_t)b * CC + c0 + ch) * PLANE + (size_t)(ys + oy) * WW + xs + ox;
        float4 v;
        if ((xs & 3) == 0) {
            v = *(const float4*)src;
        } else {
            v.x = src[0]; v.y = src[1]; v.z = src[2]; v.w = src[3];
        }
        *(float4*)(out + (((size_t)(b * CC + c0 + ch)) * LL + oy) * LL + ox) = v;
        return;
    }

    // ---------------- slow path: bilinear gather ----------------
    const int ox = threadIdx.x;
    if (ox >= LL) return;
    const int oy = blockIdx.x * 4 + threadIdx.y;

    const float fy = (float)ry * (1.0f / LL);
    const float fx = (float)rx * (1.0f / LL);

    float syv = fmaxf(((float)oy + 0.5f) * fy - 0.5f, 0.0f);
    float sxv = fmaxf(((float)ox + 0.5f) * fx - 0.5f, 0.0f);
    int y0 = (int)syv;                  // >= 0 -> trunc == floor
    int x0 = (int)sxv;
    int y1 = min(y0 + 1, ry - 1);
    int x1 = min(x0 + 1, rx - 1);
    float wy = syv - (float)y0;
    float wx = sxv - (float)x0;

    const int o00 = (ys + y0) * WW + xs + x0;
    const int o01 = (ys + y0) * WW + xs + x1;
    const int o10 = (ys + y1) * WW + xs + x0;
    const int o11 = (ys + y1) * WW + xs + x1;

    const float* __restrict__ img = in + ((size_t)b * CC + c0) * PLANE;
    float* __restrict__ obase =
        out + (((size_t)(b * CC + c0)) * LL + oy) * LL + ox;

    float v00[4], v01[4], v10[4], v11[4];
    #pragma unroll
    for (int ch = 0; ch < 4; ch++) {
        const float* __restrict__ p = img + (size_t)ch * PLANE;
        v00[ch] = p[o00];
        v01[ch] = p[o01];
        v10[ch] = p[o10];
        v11[ch] = p[o11];
    }
    #pragma unroll
    for (int ch = 0; ch < 4; ch++) {
        float top = v00[ch] * (1.0f - wx) + v01[ch] * wx;
        float bot = v10[ch] * (1.0f - wx) + v11[ch] * wx;
        obase[(size_t)ch * (LL * LL)] = top * (1.0f - wy) + bot * wy;
    }
}

extern "C" void kernel_launch(void* const* d_in, const int* in_sizes, int n_in,
                              void* d_out, int out_size) {
    const float* in = (const float*)d_in[0];
    float* out = (float*)d_out;

    reduce_pos_kernel<<<dim3(RB, BB), 256>>>(in);

    dim3 cb(128, 4);                    // 512 threads
    dim3 cg(LL / 4, CC / 4, BB);        // 30 x 8 x 32 = 7680 blocks
    crop_resize_kernel<<<cg, cb>>>(in, out);
}